// round 11
// baseline (speedup 1.0000x reference)
#include <cuda_runtime.h>

// LIF membrane recurrence, HBM-bound streaming kernel.
//   mem[t] = 0.25 * mem[t-1] * (1 - spike[t-1]) + x[t] ; spike[t] = mem[t] > 0.5
// x: (8, 32, 128, 32, 32) fp32. 134 MB read + 134 MB write, zero reuse.
//
// Floor kernel (R0/R3/R6/R7/R9): 36.1-36.7us, DRAM 75%. Closed axes:
//   .cs/.cg hints (+8.7us), sw pipeline (+2us), tile x2 / block 512 (neutral),
//   v8.b32 256-bit (+5.7us, reg pressure).
// R10: persistent grid-stride launch — exactly one wave (148 SMs x 8 CTAs =
// 1184 CTAs), eliminating the (n_waves-1)*T_wave_trans tail of the 3.46-wave
// baseline. Per-iteration body is byte-identical to the floor kernel.

#define T_STEPS 8
#define INNER   (32 * 128 * 32 * 32)   // 4,194,304 elements per timestep
#define INNER4  (INNER / 4)            // 1,048,576 float4 sites
#define NCTAS   (148 * 8)              // one full wave at occ=8
#define NTHREADS 256

__global__ void __launch_bounds__(NTHREADS, 8)
lif_kernel(const float4* __restrict__ x, float4* __restrict__ out) {
    const float DECAY = 0.25f;
    const float THR   = 0.5f;
    const int stride = NCTAS * NTHREADS;   // 303,104

    for (int i = blockIdx.x * NTHREADS + threadIdx.x; i < INNER4; i += stride) {
        // Front-batch all 8 timestep loads (independent -> MLP=8).
        float4 xv[T_STEPS];
#pragma unroll
        for (int t = 0; t < T_STEPS; ++t) {
            xv[t] = x[(size_t)t * INNER4 + i];
        }

        float m0 = 0.f, m1 = 0.f, m2 = 0.f, m3 = 0.f;
        float s0 = 0.f, s1 = 0.f, s2 = 0.f, s3 = 0.f;

#pragma unroll
        for (int t = 0; t < T_STEPS; ++t) {
            m0 = DECAY * m0 * (1.0f - s0) + xv[t].x;
            m1 = DECAY * m1 * (1.0f - s1) + xv[t].y;
            m2 = DECAY * m2 * (1.0f - s2) + xv[t].z;
            m3 = DECAY * m3 * (1.0f - s3) + xv[t].w;
            s0 = (m0 > THR) ? 1.0f : 0.0f;
            s1 = (m1 > THR) ? 1.0f : 0.0f;
            s2 = (m2 > THR) ? 1.0f : 0.0f;
            s3 = (m3 > THR) ? 1.0f : 0.0f;
            out[(size_t)t * INNER4 + i] = make_float4(s0, s1, s2, s3);
        }
    }
}

extern "C" void kernel_launch(void* const* d_in, const int* in_sizes, int n_in,
                              void* d_out, int out_size) {
    const float4* x = (const float4*)d_in[0];
    float4* out = (float4*)d_out;
    lif_kernel<<<NCTAS, NTHREADS>>>(x, out);
}

// round 12
// speedup vs baseline: 1.0560x; 1.0560x over previous
#include <cuda_runtime.h>

// LIF membrane recurrence — FINAL (committed floor, session concluded).
//   mem[0] = x[0]; mem[t] = 0.25 * mem[t-1] * (1 - spike[t-1]) + x[t]
//   spike[t] = (mem[t] > 0.5)
// x: (8, 32, 128, 32, 32) fp32. Recurrence only along t; 4,194,304 independent
// sites. 134 MB read + 134 MB write, zero reuse -> pure HBM-bound.
//
// Full search matrix (kernel time, every axis tested in isolation):
//   plain float4, front-batch 8, 4096x256 : 36.1-36.7us, DRAM 75%  << FLOOR
//   .cs ld+st / .cg loads                 : 44.7 / 45.3us (default L1/L2
//                                           caching is load-bearing)
//   sw pipeline (MLP 8->2)                : 38.1us (loop overhead > gain)
//   tile x2 / block 512                   : 37.2 / 36.1us (neutral)
//   v8.b32 256-bit ld/st                  : 41.9us (76 regs -> occ 29%)
//   persistent 1-wave grid-stride         : 38.6us (back-edge serialization;
//                                           HW CTA pipelining is free overlap)
// Effective DRAM throughput incl. deferred L2 writeback ~7.4 TB/s: saturated
// mixed-stream bandwidth. Compute <9%, tensor 0% — no lever remains; the
// 268 MB of traffic is mandatory and incompressible.

#define T_STEPS 8
#define INNER   (32 * 128 * 32 * 32)   // 4,194,304 elements per timestep
#define INNER4  (INNER / 4)            // 1,048,576 float4 sites

__global__ void lif_kernel(const float4* __restrict__ x, float4* __restrict__ out) {
    int i = blockIdx.x * blockDim.x + threadIdx.x;
    if (i >= INNER4) return;

    // Front-batch all 8 timestep loads (independent -> MLP=8).
    float4 xv[T_STEPS];
#pragma unroll
    for (int t = 0; t < T_STEPS; ++t) {
        xv[t] = x[(size_t)t * INNER4 + i];
    }

    const float DECAY = 0.25f;
    const float THR   = 0.5f;

    float m0 = 0.f, m1 = 0.f, m2 = 0.f, m3 = 0.f;
    float s0 = 0.f, s1 = 0.f, s2 = 0.f, s3 = 0.f;

#pragma unroll
    for (int t = 0; t < T_STEPS; ++t) {
        m0 = DECAY * m0 * (1.0f - s0) + xv[t].x;
        m1 = DECAY * m1 * (1.0f - s1) + xv[t].y;
        m2 = DECAY * m2 * (1.0f - s2) + xv[t].z;
        m3 = DECAY * m3 * (1.0f - s3) + xv[t].w;
        s0 = (m0 > THR) ? 1.0f : 0.0f;
        s1 = (m1 > THR) ? 1.0f : 0.0f;
        s2 = (m2 > THR) ? 1.0f : 0.0f;
        s3 = (m3 > THR) ? 1.0f : 0.0f;
        out[(size_t)t * INNER4 + i] = make_float4(s0, s1, s2, s3);
    }
}

extern "C" void kernel_launch(void* const* d_in, const int* in_sizes, int n_in,
                              void* d_out, int out_size) {
    const float4* x = (const float4*)d_in[0];
    float4* out = (float4*)d_out;
    int threads = 256;
    int blocks = (INNER4 + threads - 1) / threads;   // 4096
    lif_kernel<<<blocks, threads>>>(x, out);
}

// round 13
// speedup vs baseline: 1.0568x; 1.0007x over previous
#include <cuda_runtime.h>

// LIF membrane recurrence — committed floor kernel + max-L1 carveout hint.
//   mem[0] = x[0]; mem[t] = 0.25 * mem[t-1] * (1 - spike[t-1]) + x[t]
//   spike[t] = (mem[t] > 0.5)
// x: (8, 32, 128, 32, 32) fp32. 134 MB read + 134 MB write, zero reuse.
//
// Full search matrix (kernel time, every axis tested in isolation):
//   plain float4, front-batch 8, 4096x256 : 36.1-36.7us, DRAM ~75%  << FLOOR
//   .cs ld+st / .cg loads                 : 44.7 / 45.3us
//   sw pipeline (MLP 8->2)                : 38.1us
//   tile x2 / block 512                   : 37.2 / 36.1us (neutral)
//   v8.b32 256-bit ld/st                  : 41.9us (occ collapse)
//   persistent 1-wave grid-stride         : 38.6us (back-edge serialization)
// Effective DRAM throughput incl. deferred L2 writeback ~7.4 TB/s: saturated.
// R12: body unchanged; add host-side PreferredSharedMemoryCarveout=MaxL1
// (smem=0 kernel -> request full 228KB unified array as L1D). Zero-risk,
// graph-capture-legal (host attribute call, not a stream op).

#define T_STEPS 8
#define INNER   (32 * 128 * 32 * 32)   // 4,194,304 elements per timestep
#define INNER4  (INNER / 4)            // 1,048,576 float4 sites

__global__ void lif_kernel(const float4* __restrict__ x, float4* __restrict__ out) {
    int i = blockIdx.x * blockDim.x + threadIdx.x;
    if (i >= INNER4) return;

    // Front-batch all 8 timestep loads (independent -> MLP=8).
    float4 xv[T_STEPS];
#pragma unroll
    for (int t = 0; t < T_STEPS; ++t) {
        xv[t] = x[(size_t)t * INNER4 + i];
    }

    const float DECAY = 0.25f;
    const float THR   = 0.5f;

    float m0 = 0.f, m1 = 0.f, m2 = 0.f, m3 = 0.f;
    float s0 = 0.f, s1 = 0.f, s2 = 0.f, s3 = 0.f;

#pragma unroll
    for (int t = 0; t < T_STEPS; ++t) {
        m0 = DECAY * m0 * (1.0f - s0) + xv[t].x;
        m1 = DECAY * m1 * (1.0f - s1) + xv[t].y;
        m2 = DECAY * m2 * (1.0f - s2) + xv[t].z;
        m3 = DECAY * m3 * (1.0f - s3) + xv[t].w;
        s0 = (m0 > THR) ? 1.0f : 0.0f;
        s1 = (m1 > THR) ? 1.0f : 0.0f;
        s2 = (m2 > THR) ? 1.0f : 0.0f;
        s3 = (m3 > THR) ? 1.0f : 0.0f;
        out[(size_t)t * INNER4 + i] = make_float4(s0, s1, s2, s3);
    }
}

extern "C" void kernel_launch(void* const* d_in, const int* in_sizes, int n_in,
                              void* d_out, int out_size) {
    // Request max-L1 carveout once per call (idempotent host-side attribute;
    // not a stream operation, legal under graph capture, no allocation).
    cudaFuncSetAttribute(lif_kernel,
                         cudaFuncAttributePreferredSharedMemoryCarveout,
                         cudaSharedmemCarveoutMaxL1);

    const float4* x = (const float4*)d_in[0];
    float4* out = (float4*)d_out;
    int threads = 256;
    int blocks = (INNER4 + threads - 1) / threads;   // 4096
    lif_kernel<<<blocks, threads>>>(x, out);
}